// round 3
// baseline (speedup 1.0000x reference)
#include <cuda_runtime.h>

#define HH 256
#define WW 256
#define BB 16
#define CC 32
#define OO 32

#define TH 8            // tile rows
#define TW 64           // tile cols
#define HALO 8
#define CCH 8           // channel chunk
#define SB_ROWS (TH + 2*HALO)            // 24
#define SB_COLS (TW + 2*HALO)            // 80
#define SB_FLOATS (CCH * SB_ROWS * SB_COLS)   // 15360
#define VSTRIDE (TH*TW + 8)              // 520 (16B-aligned rows, bank-shifted)
#define VT_FLOATS (CCH * VSTRIDE)        // 4160
#define SWD_U64 (9 * CCH * 32)           // 2304
#define DEFORM_SMEM ((SB_FLOATS + 2*VT_FLOATS) * 4 + SWD_U64 * 8)  // 113152 B

// Scratch for the blurred image (B,C,H,W) fp32
__device__ float g_blur[(size_t)BB * CC * HH * WW];

typedef unsigned long long ull;

__device__ __forceinline__ ull pack2(float lo, float hi) {
    ull r;
    asm("mov.b64 %0, {%1, %2};" : "=l"(r) : "f"(lo), "f"(hi));
    return r;
}
__device__ __forceinline__ ull fma2(ull a, ull b, ull c) {
    ull d;
    asm("fma.rn.f32x2 %0, %1, %2, %3;" : "=l"(d) : "l"(a), "l"(b), "l"(c));
    return d;
}
__device__ __forceinline__ void unpack2(ull v, float& lo, float& hi) {
    asm("mov.b64 {%0, %1}, %2;" : "=f"(lo), "=f"(hi) : "l"(v));
}

// ---------------- Kernel 1: 5x5 gaussian blur (depthwise, SAME/zero pad) ----------------
__global__ __launch_bounds__(256) void blur_kernel(const float* __restrict__ x,
                                                   const float* __restrict__ sigp) {
    __shared__ float tile[36][36];
    const float sigma = *sigp;
    float wv[5];
    float s = 0.f;
#pragma unroll
    for (int i = 0; i < 5; i++) {
        float cc = (float)(i - 2);
        wv[i] = expf(-cc * cc / (2.f * sigma * sigma));
        s += wv[i];
    }
    const float inv_s2 = 1.f / (s * s);

    const int plane = blockIdx.z;                  // b*CC + c
    const int gy0 = blockIdx.y * 32 - 2;
    const int gx0 = blockIdx.x * 32 - 2;
    const float* xp = x + (size_t)plane * (HH * WW);
    const int tid = threadIdx.x + threadIdx.y * 32;  // block (32,8)

    for (int idx = tid; idx < 36 * 36; idx += 256) {
        int r = idx / 36, q = idx - r * 36;
        int gy = gy0 + r, gx = gx0 + q;
        float v = 0.f;
        if (gy >= 0 && gy < HH && gx >= 0 && gx < WW) v = xp[gy * WW + gx];
        tile[r][q] = v;
    }
    __syncthreads();

    float* op = g_blur + (size_t)plane * (HH * WW);
#pragma unroll
    for (int ry = 0; ry < 4; ry++) {
        const int row = threadIdx.y + ry * 8;
        float acc = 0.f;
#pragma unroll
        for (int i = 0; i < 5; i++) {
            float rs = 0.f;
#pragma unroll
            for (int j = 0; j < 5; j++)
                rs = fmaf(wv[j], tile[row + i][threadIdx.x + j], rs);
            acc = fmaf(wv[i], rs, acc);
        }
        op[(gy0 + 2 + row) * WW + (gx0 + 2 + threadIdx.x)] = acc * inv_s2;
    }
}

// ---------------- Kernel 2: constant-offset deformable conv ----------------
// Block: 256 threads, tile TH x TW = 512 pixels of one batch image.
// Channels processed in chunks of 8. Per tap: phase A stages bilinear-shifted
// values v[c][pix] into smem (double-buffered), phase B does a register-blocked
// channel-mix GEMM: each thread owns 8 output channels x 8 pixels (acc as
// pixel-pair f32x2), weights pre-duplicated (w,w) in smem.
__global__ __launch_bounds__(256, 2) void deform_kernel(const float* __restrict__ sigp,
                                                        const float* __restrict__ weight,
                                                        float* __restrict__ out) {
    extern __shared__ __align__(16) float smem[];
    float* sb = smem;                                  // [CCH][SB_ROWS][SB_COLS], zero halo
    float* vt = smem + SB_FLOATS;                      // [2][CCH][VSTRIDE]
    ull*   swd = (ull*)(smem + SB_FLOATS + 2 * VT_FLOATS);  // [9][CCH][32] dup pairs

    const int b   = blockIdx.z;
    const int by0 = blockIdx.y * TH;
    const int bx0 = blockIdx.x * TW;
    const int tid  = threadIdx.x;
    const int lane = tid & 31;
    const int warp = tid >> 5;

    const float sigrate = (*sigp) * 6.0f;

    // phase-B ownership: og -> 8 output channels, pg -> 8 contiguous pixels
    const int og   = tid & 3;
    const int pg   = tid >> 2;        // 0..63
    const int prow = pg >> 3;         // 0..7
    const int pcol = (pg & 7) * 8;    // 0..56

    ull acc[8][4];
#pragma unroll
    for (int j = 0; j < 8; j++)
#pragma unroll
        for (int p = 0; p < 4; p++) acc[j][p] = 0ull;

    for (int cc = 0; cc < CC / CCH; cc++) {
        __syncthreads();  // protect sb/swd (and vt) reuse across chunks

        // ---- load input chunk tile with zero halo (image-OOB -> 0) ----
        const float* gp = g_blur + ((size_t)b * CC + cc * CCH) * (HH * WW);
        for (int idx = tid; idx < SB_FLOATS; idx += 256) {
            int ci  = idx / (SB_ROWS * SB_COLS);
            int rem = idx - ci * (SB_ROWS * SB_COLS);
            int r = rem / SB_COLS;
            int q = rem - r * SB_COLS;
            int gy = by0 - HALO + r;
            int gx = bx0 - HALO + q;
            float v = 0.f;
            if (gy >= 0 && gy < HH && gx >= 0 && gx < WW)
                v = gp[ci * (HH * WW) + gy * WW + gx];
            sb[idx] = v;
        }
        // ---- load weight chunk, duplicated into (w,w) u64 ----
        for (int idx = tid; idx < SWD_U64; idx += 256) {
            int o   = idx & 31;
            int rem = idx >> 5;       // k*CCH + ci
            int ci  = rem & (CCH - 1);
            int k   = rem >> 3;
            float w = weight[(o * CC + cc * CCH + ci) * 9 + k];
            swd[idx] = pack2(w, w);
        }
        __syncthreads();

        for (int k = 0; k < 9; k++) {
            // ---- uniform tap geometry ----
            const int kyi = k / 3 - 1;
            const int kxi = k % 3 - 1;
            const float n2 = (float)(kyi * kyi + kxi * kxi);
            const float inv = (n2 > 0.f) ? (1.0f / sqrtf(n2)) : 0.0f;
            const float dy = (float)kyi + sigrate * ((float)kyi * inv);
            const float dx = (float)kxi + sigrate * ((float)kxi * inv);
            const float fy = floorf(dy), fx = floorf(dx);
            int iy = (int)fy, ix = (int)fx;
            const float ty = dy - fy, tx = dx - fx;
            iy = max(-HALO, min(iy, HALO - 1));   // safety clamp (inactive at sigma=1)
            ix = max(-HALO, min(ix, HALO - 1));
            const float w00 = (1.f - ty) * (1.f - tx);
            const float w01 = (1.f - ty) * tx;
            const float w10 = ty * (1.f - tx);
            const float w11 = ty * tx;
            const bool hx = (tx != 0.f);
            const bool hy = (ty != 0.f);

            float* vbuf = vt + (k & 1) * VT_FLOATS;

            // ---- phase A: stage shifted tile (uniform-branch skips for t==0) ----
            for (int it = warp; it < CCH * TH; it += 8) {
                const int ci = it >> 3;
                const int row = it & (TH - 1);
                const float* base = sb + (ci * SB_ROWS + row + HALO + iy) * SB_COLS
                                      + HALO + ix;
                float* vrow = vbuf + ci * VSTRIDE + row * TW;
#pragma unroll
                for (int xx0 = 0; xx0 < TW; xx0 += 32) {
                    const int xx = xx0 + lane;
                    float v = w00 * base[xx];
                    if (hx) v = fmaf(w01, base[xx + 1], v);
                    if (hy) {
                        v = fmaf(w10, base[SB_COLS + xx], v);
                        if (hx) v = fmaf(w11, base[SB_COLS + xx + 1], v);
                    }
                    vrow[xx] = v;
                }
            }
            __syncthreads();

            // ---- phase B: register-blocked 8 och x 8 pix GEMM over this chunk ----
            const ull* wk = swd + (k * CCH) * 32 + og * 8;
#pragma unroll
            for (int ci = 0; ci < CCH; ci++) {
                const ull* vp = (const ull*)(vbuf + ci * VSTRIDE + prow * TW + pcol);
                const ull v0 = vp[0], v1 = vp[1], v2 = vp[2], v3 = vp[3];
                const ull* wp = wk + ci * 32;
#pragma unroll
                for (int j = 0; j < 8; j++) {
                    const ull w = wp[j];
                    acc[j][0] = fma2(v0, w, acc[j][0]);
                    acc[j][1] = fma2(v1, w, acc[j][1]);
                    acc[j][2] = fma2(v2, w, acc[j][2]);
                    acc[j][3] = fma2(v3, w, acc[j][3]);
                }
            }
        }
    }

    // ---- epilogue: 8 och x 8 pixels per thread, vectorized stores ----
    float* ob = out + ((size_t)b * OO + og * 8) * (HH * WW)
                    + (by0 + prow) * WW + bx0 + pcol;
#pragma unroll
    for (int j = 0; j < 8; j++) {
        float4 f0, f1;
        unpack2(acc[j][0], f0.x, f0.y);
        unpack2(acc[j][1], f0.z, f0.w);
        unpack2(acc[j][2], f1.x, f1.y);
        unpack2(acc[j][3], f1.z, f1.w);
        float* p = ob + (size_t)j * (HH * WW);
        ((float4*)p)[0] = f0;
        ((float4*)p)[1] = f1;
    }
}

extern "C" void kernel_launch(void* const* d_in, const int* in_sizes, int n_in,
                              void* d_out, int out_size) {
    const float* x = nullptr;
    const float* sig = nullptr;
    const float* wgt = nullptr;
    for (int i = 0; i < n_in; i++) {
        if (in_sizes[i] == 1) sig = (const float*)d_in[i];
        else if (in_sizes[i] == OO * CC * 9) wgt = (const float*)d_in[i];
        else x = (const float*)d_in[i];
    }
    float* out = (float*)d_out;

    dim3 bgrid(WW / 32, HH / 32, BB * CC);
    blur_kernel<<<bgrid, dim3(32, 8)>>>(x, sig);

    cudaFuncSetAttribute(deform_kernel,
                         cudaFuncAttributeMaxDynamicSharedMemorySize, DEFORM_SMEM);
    dim3 dgrid(WW / TW, HH / TH, BB);
    deform_kernel<<<dgrid, 256, DEFORM_SMEM>>>(sig, wgt, out);
}

// round 6
// speedup vs baseline: 2.1250x; 2.1250x over previous
#include <cuda_runtime.h>
#include <cstdint>

#define HH 256
#define WW 256
#define BB 16
#define CC 32
#define OO 32
#define TR 8
#define TC 16

#define TSTR 36                     // tile row stride (floats), 16B aligned
#define PLANE 872                   // tile plane stride: 24*36 + 8 (bank-skewed)
#define TILE_FLOATS (16 * PLANE)    // 13952 (one 16-channel chunk)
#define WSTR 40                     // weight row stride (floats), bank-skewed
#define W_FLOATS (9 * 32 * WSTR)    // 11520
#define SMEM_DYN ((TILE_FLOATS + W_FLOATS) * 4)   // 101888 B

__device__ float g_blur[(size_t)BB * CC * HH * WW];
__device__ float g_wprep[W_FLOATS];   // [tap][kch][och] tf32-rounded, stride 40

__device__ __forceinline__ uint32_t tf32r(float f) {
    uint32_t u;
    asm("cvt.rna.tf32.f32 %0, %1;" : "=r"(u) : "f"(f));
    return u;
}
__device__ __forceinline__ void mma_tf32(float* d, const uint32_t* a,
                                         uint32_t b0, uint32_t b1) {
    asm volatile(
        "mma.sync.aligned.m16n8k8.row.col.f32.tf32.tf32.f32 "
        "{%0,%1,%2,%3}, {%4,%5,%6,%7}, {%8,%9}, {%0,%1,%2,%3};"
        : "+f"(d[0]), "+f"(d[1]), "+f"(d[2]), "+f"(d[3])
        : "r"(a[0]), "r"(a[1]), "r"(a[2]), "r"(a[3]), "r"(b0), "r"(b1));
}

// ---------------- Kernel 0: weight prep ([o][c][k] -> [k][c][o], tf32) -------------
__global__ void wprep_kernel(const float* __restrict__ w) {
    int idx = blockIdx.x * 256 + threadIdx.x;
    if (idx < OO * CC * 9) {
        int o = idx / (CC * 9);
        int rem = idx - o * (CC * 9);
        int c = rem / 9;
        int k = rem - c * 9;
        uint32_t u = tf32r(w[idx]);
        g_wprep[(k * 32 + c) * WSTR + o] = __uint_as_float(u);
    }
}

// ---------------- Kernel 1: separable 5x5 gaussian blur (SAME, zero pad) -----------
__global__ __launch_bounds__(256) void blur_kernel(const float* __restrict__ x,
                                                   const float* __restrict__ sigp) {
    __shared__ float tile[36][36];
    __shared__ float hbuf[36][32];
    const float sigma = *sigp;
    float wv[5];
    float s = 0.f;
#pragma unroll
    for (int i = 0; i < 5; i++) {
        float cc = (float)(i - 2);
        wv[i] = expf(-cc * cc / (2.f * sigma * sigma));
        s += wv[i];
    }
    const float inv_s2 = 1.f / (s * s);

    const int plane = blockIdx.z;
    const int gy0 = blockIdx.y * 32 - 2;
    const int gx0 = blockIdx.x * 32 - 2;
    const float* xp = x + (size_t)plane * (HH * WW);
    const int tid = threadIdx.x + threadIdx.y * 32;

    for (int idx = tid; idx < 36 * 36; idx += 256) {
        int r = idx / 36, q = idx - r * 36;
        int gy = gy0 + r, gx = gx0 + q;
        float v = 0.f;
        if (gy >= 0 && gy < HH && gx >= 0 && gx < WW) v = xp[gy * WW + gx];
        tile[r][q] = v;
    }
    __syncthreads();

    for (int idx = tid; idx < 36 * 32; idx += 256) {
        int r = idx >> 5, q = idx & 31;
        float a = 0.f;
#pragma unroll
        for (int j = 0; j < 5; j++) a = fmaf(wv[j], tile[r][q + j], a);
        hbuf[r][q] = a;
    }
    __syncthreads();

    float* op = g_blur + (size_t)plane * (HH * WW);
#pragma unroll
    for (int ry = 0; ry < 4; ry++) {
        const int row = threadIdx.y + ry * 8;
        float acc = 0.f;
#pragma unroll
        for (int i = 0; i < 5; i++) acc = fmaf(wv[i], hbuf[row + i][threadIdx.x], acc);
        op[(gy0 + 2 + row) * WW + (gx0 + 2 + threadIdx.x)] = acc * inv_s2;
    }
}

// ---------------- Kernel 2: deformable conv via tf32 mma.sync ----------------------
// Grid (16, 32, 16), 256 threads. Tile M=128 pixels (8 rows x 16 cols), N=32 och,
// K = 9 taps x 32 ch (chunked 16+16). Warp w owns pixel row w (16 cols); A fragments
// (bilinear samples) are computed straight into registers from the smem tile; B
// fragments come from bank-skewed smem weights. 36 mma.m16n8k8 per n-tile, acc in regs.
__global__ __launch_bounds__(256, 2) void deform_kernel(const float* __restrict__ sigp,
                                                        float* __restrict__ out) {
    extern __shared__ __align__(16) float smem[];
    float* tile = smem;                 // [16 ch][872] (24 rows x stride 36, skewed)
    float* sw = smem + TILE_FLOATS;     // [9][32][40]

    const int tid = threadIdx.x;
    const int warp = tid >> 5;          // pixel row within tile
    const int lane = tid & 31;
    const int g = lane >> 2;            // fragment group id (pixel col / och)
    const int tig = lane & 3;           // thread-in-group (channel / och pair)

    const int b = blockIdx.z;
    const int by0 = blockIdx.y * TR;
    const int bx0 = blockIdx.x * TC;

    // stage weights (vector copy, already tf32 + layout-prepped)
    {
        const float4* src = (const float4*)g_wprep;
        float4* dst = (float4*)sw;
        for (int i = tid; i < W_FLOATS / 4; i += 256) dst[i] = src[i];
    }

    float acc[4][4];
#pragma unroll
    for (int nt = 0; nt < 4; nt++)
#pragma unroll
        for (int j = 0; j < 4; j++) acc[nt][j] = 0.f;

    const float sigrate = (*sigp) * 6.0f;

    for (int chunk = 0; chunk < 2; chunk++) {
        __syncthreads();   // protect tile reuse across chunks

        // load 16-channel tile chunk, +/-8 halo, zero-filled outside image
        const float* gp = g_blur + ((size_t)b * CC + chunk * 16) * (HH * WW);
        for (int i = tid; i < 3072; i += 256) {
            int xg = i & 7;
            int y = (i >> 3) % 24;
            int c = i / 192;
            int gy = by0 - 8 + y;
            int gx = bx0 - 8 + xg * 4;
            float4 v = make_float4(0.f, 0.f, 0.f, 0.f);
            if (gy >= 0 && gy < HH && gx >= 0 && gx <= WW - 4)
                v = *(const float4*)(gp + (size_t)c * (HH * WW) + gy * WW + gx);
            *(float4*)(tile + c * PLANE + y * TSTR + xg * 4) = v;
        }
        __syncthreads();

        for (int tap = 0; tap < 9; tap++) {
            const int kyi = tap / 3 - 1;
            const int kxi = tap % 3 - 1;
            const float n2 = (float)(kyi * kyi + kxi * kxi);
            const float invn = (n2 > 0.f) ? (1.0f / sqrtf(n2)) : 0.0f;
            const float Dy = (float)kyi + sigrate * ((float)kyi * invn);
            const float Dx = (float)kxi + sigrate * ((float)kxi * invn);
            const float fy = floorf(Dy), fx = floorf(Dx);
            int iy = (int)fy, ix = (int)fx;
            const float ty = Dy - fy, tx = Dx - fx;
            iy = max(-8, min(iy, 7));   // safety clamp (inactive at sigma=1)
            ix = max(-8, min(ix, 7));
            const float w00 = (1.f - ty) * (1.f - tx);
            const float w01 = (1.f - ty) * tx;
            const float w10 = ty * (1.f - tx);
            const float w11 = ty * tx;
            const bool ipure = (tx == 0.f) && (ty == 0.f);

            // ---- A fragments: 2 k-steps x 4 regs, bilinear straight to registers --
            const float* tb = tile + (8 + warp + iy) * TSTR + (8 + ix);
            uint32_t ua[2][4];
            if (ipure) {
#pragma unroll
                for (int ks = 0; ks < 2; ks++) {
                    const float* pb = tb + (ks * 8 + tig) * PLANE;
#pragma unroll
                    for (int h = 0; h < 2; h++) {
                        const float* pc = pb + h * (4 * PLANE) + g;
                        ua[ks][h * 2 + 0] = tf32r(pc[0]);
                        ua[ks][h * 2 + 1] = tf32r(pc[8]);
                    }
                }
            } else {
#pragma unroll
                for (int ks = 0; ks < 2; ks++) {
                    const float* pb = tb + (ks * 8 + tig) * PLANE;
#pragma unroll
                    for (int h = 0; h < 2; h++) {
#pragma unroll
                        for (int m = 0; m < 2; m++) {
                            const float* p = pb + h * (4 * PLANE) + g + m * 8;
                            float v = fmaf(w11, p[TSTR + 1],
                                      fmaf(w10, p[TSTR],
                                      fmaf(w01, p[1], w00 * p[0])));
                            ua[ks][h * 2 + m] = tf32r(v);
                        }
                    }
                }
            }

            // ---- B fragments + mma ----
            const float* wb = sw + (tap * 32 + chunk * 16) * WSTR;
#pragma unroll
            for (int nt = 0; nt < 4; nt++) {
                const int och = nt * 8 + g;
#pragma unroll
                for (int ks = 0; ks < 2; ks++) {
                    const float* bp = wb + (ks * 8 + tig) * WSTR + och;
                    uint32_t b0 = __float_as_uint(bp[0]);
                    uint32_t b1 = __float_as_uint(bp[4 * WSTR]);
                    mma_tf32(acc[nt], ua[ks], b0, b1);
                }
            }
        }
    }

    // ---- epilogue: thread holds (pixel cols g, g+8) x (och 2*tig, 2*tig+1) x 4 nt --
    const int gy = by0 + warp;
    float* ob = out + (size_t)b * OO * (HH * WW) + (size_t)gy * WW + bx0 + g;
#pragma unroll
    for (int nt = 0; nt < 4; nt++) {
        const int och = nt * 8 + 2 * tig;
        float* p0 = ob + (size_t)och * (HH * WW);
        float* p1 = p0 + (size_t)(HH * WW);
        p0[0] = acc[nt][0];
        p1[0] = acc[nt][1];
        p0[8] = acc[nt][2];
        p1[8] = acc[nt][3];
    }
}

extern "C" void kernel_launch(void* const* d_in, const int* in_sizes, int n_in,
                              void* d_out, int out_size) {
    const float* x = nullptr;
    const float* sig = nullptr;
    const float* wgt = nullptr;
    for (int i = 0; i < n_in; i++) {
        if (in_sizes[i] == 1) sig = (const float*)d_in[i];
        else if (in_sizes[i] == OO * CC * 9) wgt = (const float*)d_in[i];
        else x = (const float*)d_in[i];
    }
    float* out = (float*)d_out;

    wprep_kernel<<<36, 256>>>(wgt);

    dim3 bgrid(WW / 32, HH / 32, BB * CC);
    blur_kernel<<<bgrid, dim3(32, 8)>>>(x, sig);

    cudaFuncSetAttribute(deform_kernel,
                         cudaFuncAttributeMaxDynamicSharedMemorySize, SMEM_DYN);
    dim3 dgrid(WW / TC, HH / TR, BB);
    deform_kernel<<<dgrid, 256, SMEM_DYN>>>(sig, out);
}

// round 7
// speedup vs baseline: 3.0129x; 1.4178x over previous
#include <cuda_runtime.h>
#include <cstdint>

#define HH 256
#define WW 256
#define BB 16
#define CC 32
#define OO 32
#define TR 16                       // tile pixel rows
#define TC 32                       // tile pixel cols
#define CCH 8                       // channel chunk

#define TSTR 48                     // tile row stride (floats)
#define PLANE 1544                  // 32*48 + 8 skew
#define TILE_FLOATS (CCH * PLANE)   // 12352
#define W_F2 (4 * 9 * 32 * 4)       // 4608 float2 (chunk, tap, och, tig)
#define SMEM_DYN (TILE_FLOATS * 4 + W_F2 * 8)   // 86272 B

__device__ float g_blur[(size_t)BB * CC * HH * WW];
__device__ float2 g_wprep[W_F2];

__device__ __forceinline__ uint32_t tf32r(float f) {
    uint32_t u;
    asm("cvt.rna.tf32.f32 %0, %1;" : "=r"(u) : "f"(f));
    return u;
}
__device__ __forceinline__ void mma_tf32(float* d, const uint32_t* a,
                                         uint32_t b0, uint32_t b1) {
    asm volatile(
        "mma.sync.aligned.m16n8k8.row.col.f32.tf32.tf32.f32 "
        "{%0,%1,%2,%3}, {%4,%5,%6,%7}, {%8,%9}, {%0,%1,%2,%3};"
        : "+f"(d[0]), "+f"(d[1]), "+f"(d[2]), "+f"(d[3])
        : "r"(a[0]), "r"(a[1]), "r"(a[2]), "r"(a[3]), "r"(b0), "r"(b1));
}

// --------- Kernel 0: weight prep -> float2(b0,b1) [chunk][tap][och][tig], tf32 -----
__global__ void wprep_kernel(const float* __restrict__ w) {
    int idx = blockIdx.x * 256 + threadIdx.x;
    if (idx < OO * CC * 9) {
        int o = idx / (CC * 9);
        int rem = idx - o * (CC * 9);
        int c = rem / 9;
        int k = rem - c * 9;
        int chunk = c >> 3;
        int kc = c & 7;
        int tig = kc & 3;
        int half = kc >> 2;          // 0 -> b0 (kch=tig), 1 -> b1 (kch=tig+4)
        float* dst = (float*)&g_wprep[((chunk * 9 + k) * 32 + o) * 4 + tig];
        dst[half] = __uint_as_float(tf32r(w[idx]));
    }
}

// --------- Kernel 1: separable 5x5 gaussian blur (SAME, zero pad) ------------------
__global__ __launch_bounds__(256) void blur_kernel(const float* __restrict__ x,
                                                   const float* __restrict__ sigp) {
    __shared__ float tile[36][36];
    __shared__ float hbuf[36][32];
    const float sigma = *sigp;
    float wv[5];
    float s = 0.f;
#pragma unroll
    for (int i = 0; i < 5; i++) {
        float cc = (float)(i - 2);
        wv[i] = expf(-cc * cc / (2.f * sigma * sigma));
        s += wv[i];
    }
    const float inv_s2 = 1.f / (s * s);

    const int plane = blockIdx.z;
    const int gy0 = blockIdx.y * 32 - 2;
    const int gx0 = blockIdx.x * 32 - 2;
    const float* xp = x + (size_t)plane * (HH * WW);
    const int tid = threadIdx.x + threadIdx.y * 32;

    for (int idx = tid; idx < 36 * 36; idx += 256) {
        int r = idx / 36, q = idx - r * 36;
        int gy = gy0 + r, gx = gx0 + q;
        float v = 0.f;
        if (gy >= 0 && gy < HH && gx >= 0 && gx < WW) v = xp[gy * WW + gx];
        tile[r][q] = v;
    }
    __syncthreads();

    for (int idx = tid; idx < 36 * 32; idx += 256) {
        int r = idx >> 5, q = idx & 31;
        float a = 0.f;
#pragma unroll
        for (int j = 0; j < 5; j++) a = fmaf(wv[j], tile[r][q + j], a);
        hbuf[r][q] = a;
    }
    __syncthreads();

    float* op = g_blur + (size_t)plane * (HH * WW);
#pragma unroll
    for (int ry = 0; ry < 4; ry++) {
        const int row = threadIdx.y + ry * 8;
        float acc = 0.f;
#pragma unroll
        for (int i = 0; i < 5; i++) acc = fmaf(wv[i], hbuf[row + i][threadIdx.x], acc);
        op[(gy0 + 2 + row) * WW + (gx0 + 2 + threadIdx.x)] = acc * inv_s2;
    }
}

// --------- Kernel 2: deformable conv via tf32 mma.sync, M=512 tiles ---------------
// Grid (8, 16, 16), 256 threads. Tile 16x32 = 512 px, N=32 och, K = 9 taps x 32 ch
// (4 chunks of 8 -> one k8 step each). Warp w owns pixel rows {2w, 2w+1}; 4 m16
// fragments per warp (row rr, col-half cc). A bilinear samples go straight to regs;
// B is one conflict-free LDS.64 per (tap, nt) shared by all 4 fragments.
__global__ __launch_bounds__(256, 2) void deform_kernel(const float* __restrict__ sigp,
                                                        float* __restrict__ out) {
    extern __shared__ __align__(16) float smem[];
    float* tile = smem;                         // [8 ch][1544]
    float2* swf = (float2*)(smem + TILE_FLOATS);  // [4][9][32][4]

    const int tid = threadIdx.x;
    const int warp = tid >> 5;
    const int lane = tid & 31;
    const int g = lane >> 2;
    const int tig = lane & 3;

    const int b = blockIdx.z;
    const int by0 = blockIdx.y * TR;
    const int bx0 = blockIdx.x * TC;

    // stage all weights once (vector copy)
    {
        const float4* src = (const float4*)g_wprep;
        float4* dst = (float4*)swf;
        for (int i = tid; i < W_F2 / 2; i += 256) dst[i] = src[i];
    }

    float acc[2][2][4][4];
#pragma unroll
    for (int rr = 0; rr < 2; rr++)
#pragma unroll
        for (int cc = 0; cc < 2; cc++)
#pragma unroll
            for (int nt = 0; nt < 4; nt++)
#pragma unroll
                for (int j = 0; j < 4; j++) acc[rr][cc][nt][j] = 0.f;

    const float sigrate = (*sigp) * 6.0f;

    for (int chunk = 0; chunk < 4; chunk++) {
        __syncthreads();   // protect tile reuse across chunks (also orders W copy)

        // load 8-channel tile chunk, +/-8 halo, zero outside image
        const float* gp = g_blur + ((size_t)b * CC + chunk * CCH) * (HH * WW);
        for (int i = tid; i < 3072; i += 256) {
            int xg = i % 12;
            int t = i / 12;
            int y = t & 31;
            int c = t >> 5;
            int gy = by0 - 8 + y;
            int gx = bx0 - 8 + xg * 4;
            float4 v = make_float4(0.f, 0.f, 0.f, 0.f);
            if (gy >= 0 && gy < HH && gx >= 0 && gx <= WW - 4)
                v = *(const float4*)(gp + (size_t)c * (HH * WW) + gy * WW + gx);
            *(float4*)(tile + c * PLANE + y * TSTR + xg * 4) = v;
        }
        __syncthreads();

        for (int tap = 0; tap < 9; tap++) {
            const int kyi = tap / 3 - 1;
            const int kxi = tap % 3 - 1;
            const float n2 = (float)(kyi * kyi + kxi * kxi);
            const float invn = (n2 > 0.f) ? (1.0f / sqrtf(n2)) : 0.0f;
            const float Dy = (float)kyi + sigrate * ((float)kyi * invn);
            const float Dx = (float)kxi + sigrate * ((float)kxi * invn);
            const float fy = floorf(Dy), fx = floorf(Dx);
            int iy = (int)fy, ix = (int)fx;
            const float ty = Dy - fy, tx = Dx - fx;
            iy = max(-8, min(iy, 7));   // safety clamp (inactive at sigma=1)
            ix = max(-8, min(ix, 7));
            const float w00 = (1.f - ty) * (1.f - tx);
            const float w01 = (1.f - ty) * tx;
            const float w10 = ty * (1.f - tx);
            const float w11 = ty * tx;
            const bool ipure = (tx == 0.f) && (ty == 0.f);

            // B fragments: one LDS.64 per nt, shared across all 4 m-fragments
            float2 bv[4];
            const float2* wb = swf + (chunk * 9 + tap) * 128 + tig;
#pragma unroll
            for (int nt = 0; nt < 4; nt++) bv[nt] = wb[(nt * 8 + g) * 4];

#pragma unroll
            for (int rr = 0; rr < 2; rr++) {
#pragma unroll
                for (int cc = 0; cc < 2; cc++) {
                    const float* p0 = tile + tig * PLANE
                                    + (8 + 2 * warp + rr + iy) * TSTR
                                    + (8 + ix) + cc * 16 + g;
                    uint32_t ua[4];
                    if (ipure) {
                        ua[0] = tf32r(p0[0]);
                        ua[1] = tf32r(p0[8]);
                        ua[2] = tf32r(p0[4 * PLANE]);
                        ua[3] = tf32r(p0[4 * PLANE + 8]);
                    } else {
#pragma unroll
                        for (int h = 0; h < 2; h++) {
#pragma unroll
                            for (int m = 0; m < 2; m++) {
                                const float* p = p0 + h * (4 * PLANE) + m * 8;
                                float v = fmaf(w11, p[TSTR + 1],
                                          fmaf(w10, p[TSTR],
                                          fmaf(w01, p[1], w00 * p[0])));
                                ua[h * 2 + m] = tf32r(v);
                            }
                        }
                    }
#pragma unroll
                    for (int nt = 0; nt < 4; nt++)
                        mma_tf32(acc[rr][cc][nt], ua,
                                 __float_as_uint(bv[nt].x),
                                 __float_as_uint(bv[nt].y));
                }
            }
        }
    }

    // epilogue: fragment (rr,cc,nt): rows 2w+rr, cols cc*16+g(+8), och nt*8+2tig(+1)
#pragma unroll
    for (int rr = 0; rr < 2; rr++) {
        const int gy = by0 + 2 * warp + rr;
        float* ob = out + (size_t)b * OO * (HH * WW) + (size_t)gy * WW + bx0;
#pragma unroll
        for (int cc = 0; cc < 2; cc++) {
            float* oc = ob + cc * 16 + g;
#pragma unroll
            for (int nt = 0; nt < 4; nt++) {
                const int och = nt * 8 + 2 * tig;
                float* p0 = oc + (size_t)och * (HH * WW);
                float* p1 = p0 + (size_t)(HH * WW);
                p0[0] = acc[rr][cc][nt][0];
                p1[0] = acc[rr][cc][nt][1];
                p0[8] = acc[rr][cc][nt][2];
                p1[8] = acc[rr][cc][nt][3];
            }
        }
    }
}

extern "C" void kernel_launch(void* const* d_in, const int* in_sizes, int n_in,
                              void* d_out, int out_size) {
    const float* x = nullptr;
    const float* sig = nullptr;
    const float* wgt = nullptr;
    for (int i = 0; i < n_in; i++) {
        if (in_sizes[i] == 1) sig = (const float*)d_in[i];
        else if (in_sizes[i] == OO * CC * 9) wgt = (const float*)d_in[i];
        else x = (const float*)d_in[i];
    }
    float* out = (float*)d_out;

    wprep_kernel<<<36, 256>>>(wgt);

    dim3 bgrid(WW / 32, HH / 32, BB * CC);
    blur_kernel<<<bgrid, dim3(32, 8)>>>(x, sig);

    cudaFuncSetAttribute(deform_kernel,
                         cudaFuncAttributeMaxDynamicSharedMemorySize, SMEM_DYN);
    dim3 dgrid(WW / TC, HH / TR, BB);
    deform_kernel<<<dgrid, 256, SMEM_DYN>>>(sig, out);
}

// round 8
// speedup vs baseline: 3.8900x; 1.2911x over previous
#include <cuda_runtime.h>
#include <cstdint>

#define HH 256
#define WW 256
#define BB 16
#define CC 32
#define OO 32
#define TR 16
#define TC 32
#define CCH 8

#define ROWS 32                          // tile y: 16 + 2*8 halo
#define COLS 48                          // tile x: 32 + 2*8 halo
#define TILE_FLOATS (ROWS * COLS * CCH)  // 12288
#define W_F2 (4 * 9 * 32 * 4)            // 4608 float2
#define GEOM_OFF (TILE_FLOATS * 4 + W_F2 * 8)          // 86016
#define SMEM_DYN (GEOM_OFF + 9 * 48)                    // 86448 B

// g_blur layout: [b][chunk4][y][x][ch8]
__device__ float g_blur[(size_t)BB * CC * HH * WW];
__device__ float2 g_wprep[W_F2];

typedef unsigned long long ull;

__device__ __forceinline__ ull pack2(float lo, float hi) {
    ull r; asm("mov.b64 %0, {%1, %2};" : "=l"(r) : "f"(lo), "f"(hi)); return r;
}
__device__ __forceinline__ void unpack2(ull v, float& lo, float& hi) {
    asm("mov.b64 {%0, %1}, %2;" : "=f"(lo), "=f"(hi) : "l"(v));
}
__device__ __forceinline__ ull fma2(ull a, ull b, ull c) {
    ull d; asm("fma.rn.f32x2 %0, %1, %2, %3;" : "=l"(d) : "l"(a), "l"(b), "l"(c));
    return d;
}
__device__ __forceinline__ ull mul2(ull a, ull b) {
    ull d; asm("mul.rn.f32x2 %0, %1, %2;" : "=l"(d) : "l"(a), "l"(b)); return d;
}
__device__ __forceinline__ uint32_t tf32r(float f) {
    uint32_t u; asm("cvt.rna.tf32.f32 %0, %1;" : "=r"(u) : "f"(f)); return u;
}
__device__ __forceinline__ uint32_t s2u(const void* p) {
    uint32_t a;
    asm("{ .reg .u64 t; cvta.to.shared.u64 t, %1; cvt.u32.u64 %0, t; }"
        : "=r"(a) : "l"(p));
    return a;
}
__device__ __forceinline__ void cpasync16(uint32_t dst, const void* src, int sz) {
    asm volatile("cp.async.cg.shared.global [%0], [%1], 16, %2;"
                 :: "r"(dst), "l"(src), "r"(sz) : "memory");
}
__device__ __forceinline__ void mma_tf32(float* d, const uint32_t* a,
                                         uint32_t b0, uint32_t b1) {
    asm volatile(
        "mma.sync.aligned.m16n8k8.row.col.f32.tf32.tf32.f32 "
        "{%0,%1,%2,%3}, {%4,%5,%6,%7}, {%8,%9}, {%0,%1,%2,%3};"
        : "+f"(d[0]), "+f"(d[1]), "+f"(d[2]), "+f"(d[3])
        : "r"(a[0]), "r"(a[1]), "r"(a[2]), "r"(a[3]), "r"(b0), "r"(b1));
}

// --------- Kernel 0: weight prep. float2(b0,b1) = (w[ch 2tig], w[ch 2tig+1]) --------
__global__ void wprep_kernel(const float* __restrict__ w) {
    int idx = blockIdx.x * 256 + threadIdx.x;
    if (idx < OO * CC * 9) {
        int o = idx / (CC * 9);
        int rem = idx - o * (CC * 9);
        int c = rem / 9;
        int k = rem - c * 9;
        int chunk = c >> 3;
        int kc = c & 7;
        int tig = kc >> 1;
        int half = kc & 1;
        float* dst = (float*)&g_wprep[((chunk * 9 + k) * 32 + o) * 4 + tig];
        dst[half] = __uint_as_float(tf32r(w[idx]));
    }
}

// --------- Kernel 1: separable 5x5 blur, channel pairs in f32x2 --------------------
// grid (8,8,256): z = b*16 + cp, processes channels (2cp, 2cp+1).
__global__ __launch_bounds__(256) void blur_kernel(const float* __restrict__ x,
                                                   const float* __restrict__ sigp) {
    __shared__ ull tile2[36][36];
    __shared__ ull hbuf[36][32];
    const float sigma = *sigp;
    float wv[5];
    float s = 0.f;
#pragma unroll
    for (int i = 0; i < 5; i++) {
        float cc = (float)(i - 2);
        wv[i] = expf(-cc * cc / (2.f * sigma * sigma));
        s += wv[i];
    }
    const float inv_s2 = 1.f / (s * s);
    ull wp[5];
#pragma unroll
    for (int i = 0; i < 5; i++) wp[i] = pack2(wv[i], wv[i]);
    const ull invp = pack2(inv_s2, inv_s2);

    const int z = blockIdx.z;
    const int b = z >> 4;
    const int cp = z & 15;
    const int c0 = 2 * cp;
    const int gy0 = blockIdx.y * 32 - 2;
    const int gx0 = blockIdx.x * 32 - 2;
    const float* xp0 = x + ((size_t)b * CC + c0) * (HH * WW);
    const float* xp1 = xp0 + (HH * WW);
    const int tid = threadIdx.x + threadIdx.y * 32;

    for (int idx = tid; idx < 36 * 36; idx += 256) {
        int r = idx / 36, q = idx - r * 36;
        int gy = gy0 + r, gx = gx0 + q;
        float lo = 0.f, hi = 0.f;
        if (gy >= 0 && gy < HH && gx >= 0 && gx < WW) {
            lo = xp0[gy * WW + gx];
            hi = xp1[gy * WW + gx];
        }
        tile2[r][q] = pack2(lo, hi);
    }
    __syncthreads();

    for (int idx = tid; idx < 36 * 32; idx += 256) {
        int r = idx >> 5, q = idx & 31;
        ull a = mul2(wp[0], tile2[r][q]);
#pragma unroll
        for (int j = 1; j < 5; j++) a = fma2(wp[j], tile2[r][q + j], a);
        hbuf[r][q] = a;
    }
    __syncthreads();

    const int chunk = cp >> 2;
    const int ci = 2 * (cp & 3);
    float* gb = g_blur + ((size_t)b * 4 + chunk) * (HH * WW * 8);
#pragma unroll
    for (int ry = 0; ry < 4; ry++) {
        const int row = threadIdx.y + ry * 8;
        ull a = mul2(wp[0], hbuf[row][threadIdx.x]);
#pragma unroll
        for (int i = 1; i < 5; i++) a = fma2(wp[i], hbuf[row + i][threadIdx.x], a);
        a = mul2(a, invp);
        float lo, hi;
        unpack2(a, lo, hi);
        const int gy = gy0 + 2 + row, gx = gx0 + 2 + threadIdx.x;
        *(float2*)(gb + ((size_t)gy * WW + gx) * 8 + ci) = make_float2(lo, hi);
    }
}

// --------- Kernel 2: deformable conv, tf32 mma.sync, ch-interleaved tile -----------
__global__ __launch_bounds__(256, 2) void deform_kernel(const float* __restrict__ sigp,
                                                        float* __restrict__ out) {
    extern __shared__ __align__(16) float smem[];
    float* tile = smem;                               // [32 y][48 x][8 ch]
    float2* swf = (float2*)(smem + TILE_FLOATS);      // [4][9][32 och][4 tig]
    int* geom = (int*)((char*)smem + GEOM_OFF);       // 9 x {iy,ix,ipure,pad,4xull}
    const uint32_t tile_u = s2u(smem);

    const int tid = threadIdx.x;
    const int warp = tid >> 5;
    const int lane = tid & 31;
    const int g = lane >> 2;
    const int tig = lane & 3;

    const int b = blockIdx.z;
    const int by0 = blockIdx.y * TR;
    const int bx0 = blockIdx.x * TC;

    // stage weights
    {
        const float4* src = (const float4*)g_wprep;
        float4* dst = (float4*)swf;
        for (int i = tid; i < W_F2 / 2; i += 256) dst[i] = src[i];
    }
    // tap geometry, once
    if (tid < 9) {
        const float sigrate = (*sigp) * 6.0f;
        const int kyi = tid / 3 - 1;
        const int kxi = tid % 3 - 1;
        const float n2 = (float)(kyi * kyi + kxi * kxi);
        const float invn = (n2 > 0.f) ? (1.0f / sqrtf(n2)) : 0.0f;
        const float Dy = (float)kyi + sigrate * ((float)kyi * invn);
        const float Dx = (float)kxi + sigrate * ((float)kxi * invn);
        const float fy = floorf(Dy), fx = floorf(Dx);
        int iy = (int)fy, ix = (int)fx;
        const float ty = Dy - fy, tx = Dx - fx;
        iy = max(-8, min(iy, 7));
        ix = max(-8, min(ix, 7));
        int* gm = geom + tid * 12;
        gm[0] = iy;
        gm[1] = ix;
        gm[2] = (tx == 0.f && ty == 0.f) ? 1 : 0;
        ull* gw = (ull*)(gm + 4);
        float a00 = (1.f - ty) * (1.f - tx), a01 = (1.f - ty) * tx;
        float a10 = ty * (1.f - tx), a11 = ty * tx;
        gw[0] = pack2(a00, a00);
        gw[1] = pack2(a01, a01);
        gw[2] = pack2(a10, a10);
        gw[3] = pack2(a11, a11);
    }

    float acc[2][2][4][4];
#pragma unroll
    for (int rr = 0; rr < 2; rr++)
#pragma unroll
        for (int cc = 0; cc < 2; cc++)
#pragma unroll
            for (int nt = 0; nt < 4; nt++)
#pragma unroll
                for (int j = 0; j < 4; j++) acc[rr][cc][nt][j] = 0.f;

    for (int chunk = 0; chunk < 4; chunk++) {
        __syncthreads();   // tile reuse + (first iter) weights/geometry visibility

        // stage 8-ch tile chunk via cp.async, zero-fill outside image
        const float* gp = g_blur + ((size_t)b * 4 + chunk) * (HH * WW * 8);
        for (int i = tid; i < 3072; i += 256) {
            const int h = i & 1;
            const int px = i >> 1;
            const int xx = px % COLS;
            const int y = px / COLS;
            const int gy = by0 - 8 + y;
            const int gx = bx0 - 8 + xx;
            const int inb = (gy >= 0 && gy < HH && gx >= 0 && gx < WW) ? 16 : 0;
            cpasync16(tile_u + i * 16,
                      gp + ((size_t)gy * WW + gx) * 8 + h * 4, inb);
        }
        asm volatile("cp.async.commit_group;");
        asm volatile("cp.async.wait_group 0;" ::: "memory");
        __syncthreads();

        for (int tap = 0; tap < 9; tap++) {
            const int* gm = geom + tap * 12;
            const int iy = gm[0], ix = gm[1], ipure = gm[2];
            const ull* gw = (const ull*)(gm + 4);
            const ull a00 = gw[0], a01 = gw[1], a10 = gw[2], a11 = gw[3];

            // B fragments (k-permuted ch pairs), one LDS.64 per nt
            float2 bv[4];
            const float2* wb = swf + (chunk * 9 + tap) * 128 + tig;
#pragma unroll
            for (int nt = 0; nt < 4; nt++) bv[nt] = wb[(nt * 8 + g) * 4];

#pragma unroll
            for (int rr = 0; rr < 2; rr++) {
#pragma unroll
                for (int cc = 0; cc < 2; cc++) {
                    const int row = 2 * warp + rr + iy + 8;
                    const int col = cc * 16 + g + ix + 8;
                    const ull* p0 = (const ull*)(tile + (row * COLS + col) * CCH)
                                  + tig;
                    ull vg, vg8;
                    if (ipure) {
                        vg = p0[0];
                        vg8 = p0[32];
                    } else {
                        vg = fma2(a11, p0[196],
                             fma2(a10, p0[192],
                             fma2(a01, p0[4], mul2(a00, p0[0]))));
                        vg8 = fma2(a11, p0[228],
                              fma2(a10, p0[224],
                              fma2(a01, p0[36], mul2(a00, p0[32]))));
                    }
                    float f0, f1, f2, f3;
                    unpack2(vg, f0, f2);
                    unpack2(vg8, f1, f3);
                    uint32_t ua[4] = { __float_as_uint(f0), __float_as_uint(f1),
                                       __float_as_uint(f2), __float_as_uint(f3) };
#pragma unroll
                    for (int nt = 0; nt < 4; nt++)
                        mma_tf32(acc[rr][cc][nt], ua,
                                 __float_as_uint(bv[nt].x),
                                 __float_as_uint(bv[nt].y));
                }
            }
        }
    }

    // epilogue (mapping unchanged from passing R7 kernel)
#pragma unroll
    for (int rr = 0; rr < 2; rr++) {
        const int gy = by0 + 2 * warp + rr;
        float* ob = out + (size_t)b * OO * (HH * WW) + (size_t)gy * WW + bx0;
#pragma unroll
        for (int cc = 0; cc < 2; cc++) {
            float* oc = ob + cc * 16 + g;
#pragma unroll
            for (int nt = 0; nt < 4; nt++) {
                const int och = nt * 8 + 2 * tig;
                float* p0 = oc + (size_t)och * (HH * WW);
                float* p1 = p0 + (size_t)(HH * WW);
                p0[0] = acc[rr][cc][nt][0];
                p1[0] = acc[rr][cc][nt][1];
                p0[8] = acc[rr][cc][nt][2];
                p1[8] = acc[rr][cc][nt][3];
            }
        }
    }
}

extern "C" void kernel_launch(void* const* d_in, const int* in_sizes, int n_in,
                              void* d_out, int out_size) {
    const float* x = nullptr;
    const float* sig = nullptr;
    const float* wgt = nullptr;
    for (int i = 0; i < n_in; i++) {
        if (in_sizes[i] == 1) sig = (const float*)d_in[i];
        else if (in_sizes[i] == OO * CC * 9) wgt = (const float*)d_in[i];
        else x = (const float*)d_in[i];
    }
    float* out = (float*)d_out;

    wprep_kernel<<<36, 256>>>(wgt);

    dim3 bgrid(WW / 32, HH / 32, BB * 16);
    blur_kernel<<<bgrid, dim3(32, 8)>>>(x, sig);

    cudaFuncSetAttribute(deform_kernel,
                         cudaFuncAttributeMaxDynamicSharedMemorySize, SMEM_DYN);
    dim3 dgrid(WW / TC, HH / TR, BB);
    deform_kernel<<<dgrid, 256, SMEM_DYN>>>(sig, out);
}

// round 9
// speedup vs baseline: 5.0164x; 1.2896x over previous
#include <cuda_runtime.h>
#include <cuda_fp16.h>
#include <cstdint>

#define HH 256
#define WW 256
#define BB 16
#define CC 32
#define OO 32
#define TR 16
#define TC 32

#define ROWS 32                      // tile y: 16 + 2*8 halo
#define COLS 48                      // tile x: 32 + 2*8 halo
#define TILE_BYTES (ROWS * COLS * 16 * 2)       // 49152 (16 ch halfs / px)
#define SWF_OFF  TILE_BYTES                      // weights: [2][9][32][4] ull
#define SWF_BYTES (2 * 9 * 32 * 4 * 8)           // 18432
#define GEOM_OFF (SWF_OFF + SWF_BYTES)           // 67584
#define SMEM_DYN (GEOM_OFF + 9 * 32)             // 67872

// blur dynamic smem: tile2 (36*36 ull) + hbuf (36*32 ull) + obuf (8*1024 half2)
#define B_TILE2_ULL (36 * 36)
#define B_HBUF_ULL  (36 * 32)
#define B_OBUF_OFF  ((B_TILE2_ULL + B_HBUF_ULL) * 8)     // 19584
#define B_SMEM_DYN  (B_OBUF_OFF + 8 * 1024 * 4)          // 52352

// g_blur: [b][g16(2)][y][x][16 ch] halfs
__device__ __half g_blur[(size_t)BB * 2 * HH * WW * 16];
__device__ __half g_wprep[2 * 9 * 32 * 16];

typedef unsigned long long ull;

__device__ __forceinline__ ull pack2(float lo, float hi) {
    ull r; asm("mov.b64 %0, {%1, %2};" : "=l"(r) : "f"(lo), "f"(hi)); return r;
}
__device__ __forceinline__ void unpack2(ull v, float& lo, float& hi) {
    asm("mov.b64 {%0, %1}, %2;" : "=f"(lo), "=f"(hi) : "l"(v));
}
__device__ __forceinline__ ull fma2(ull a, ull b, ull c) {
    ull d; asm("fma.rn.f32x2 %0, %1, %2, %3;" : "=l"(d) : "l"(a), "l"(b), "l"(c));
    return d;
}
__device__ __forceinline__ ull mul2(ull a, ull b) {
    ull d; asm("mul.rn.f32x2 %0, %1, %2;" : "=l"(d) : "l"(a), "l"(b)); return d;
}
__device__ __forceinline__ uint32_t s2u(const void* p) {
    uint32_t a;
    asm("{ .reg .u64 t; cvta.to.shared.u64 t, %1; cvt.u32.u64 %0, t; }"
        : "=r"(a) : "l"(p));
    return a;
}
__device__ __forceinline__ void cpasync16(uint32_t dst, const void* src, int sz) {
    asm volatile("cp.async.cg.shared.global [%0], [%1], 16, %2;"
                 :: "r"(dst), "l"(src), "r"(sz) : "memory");
}
__device__ __forceinline__ void mma_f16(float* d, uint32_t a0, uint32_t a1,
                                        uint32_t a2, uint32_t a3,
                                        uint32_t b0, uint32_t b1) {
    asm volatile(
        "mma.sync.aligned.m16n8k16.row.col.f32.f16.f16.f32 "
        "{%0,%1,%2,%3}, {%4,%5,%6,%7}, {%8,%9}, {%0,%1,%2,%3};"
        : "+f"(d[0]), "+f"(d[1]), "+f"(d[2]), "+f"(d[3])
        : "r"(a0), "r"(a1), "r"(a2), "r"(a3), "r"(b0), "r"(b1));
}

// --------- Kernel 0: weight prep -> half [g16][tap][och][tig][4 ch] -----------------
__global__ void wprep_kernel(const float* __restrict__ w) {
    int idx = blockIdx.x * 256 + threadIdx.x;
    if (idx < OO * CC * 9) {
        int o = idx / (CC * 9);
        int rem = idx - o * (CC * 9);
        int c = rem / 9;
        int k = rem - c * 9;
        int g16 = c >> 4;
        int ci = c & 15;
        g_wprep[(((g16 * 9 + k) * 32 + o) * 4 + (ci >> 2)) * 4 + (ci & 3)] =
            __float2half(w[idx]);
    }
}

// --------- Kernel 1: separable 5x5 blur, 16 channels/block, coalesced half out -----
// grid (8,8,BB*2): z = b*2 + g16. Loops 8 channel-pairs; assembles [px][ch16] in obuf.
__global__ __launch_bounds__(256) void blur_kernel(const float* __restrict__ x,
                                                   const float* __restrict__ sigp) {
    extern __shared__ __align__(16) char bsm[];
    ull* tile2 = (ull*)bsm;                          // [36][36]
    ull* hbuf = tile2 + B_TILE2_ULL;                 // [36][32]
    __half2* obuf = (__half2*)(bsm + B_OBUF_OFF);    // [8 pair][1024 px]

    const float sigma = *sigp;
    float wv[5];
    float s = 0.f;
#pragma unroll
    for (int i = 0; i < 5; i++) {
        float cc = (float)(i - 2);
        wv[i] = expf(-cc * cc / (2.f * sigma * sigma));
        s += wv[i];
    }
    const float inv_s2 = 1.f / (s * s);
    ull wp[5];
#pragma unroll
    for (int i = 0; i < 5; i++) wp[i] = pack2(wv[i], wv[i]);
    const ull invp = pack2(inv_s2, inv_s2);

    const int z = blockIdx.z;
    const int b = z >> 1;
    const int g16 = z & 1;
    const int gy0 = blockIdx.y * 32 - 2;
    const int gx0 = blockIdx.x * 32 - 2;
    const int tid = threadIdx.x + threadIdx.y * 32;

    for (int cp2 = 0; cp2 < 8; cp2++) {
        __syncthreads();
        const int c0 = g16 * 16 + 2 * cp2;
        const float* xp0 = x + ((size_t)b * CC + c0) * (HH * WW);
        const float* xp1 = xp0 + (HH * WW);

        for (int idx = tid; idx < 36 * 36; idx += 256) {
            int r = idx / 36, q = idx - r * 36;
            int gy = gy0 + r, gx = gx0 + q;
            float lo = 0.f, hi = 0.f;
            if (gy >= 0 && gy < HH && gx >= 0 && gx < WW) {
                lo = xp0[gy * WW + gx];
                hi = xp1[gy * WW + gx];
            }
            tile2[r * 36 + q] = pack2(lo, hi);
        }
        __syncthreads();

        for (int idx = tid; idx < 36 * 32; idx += 256) {
            int r = idx >> 5, q = idx & 31;
            ull a = mul2(wp[0], tile2[r * 36 + q]);
#pragma unroll
            for (int j = 1; j < 5; j++) a = fma2(wp[j], tile2[r * 36 + q + j], a);
            hbuf[idx] = a;
        }
        __syncthreads();

#pragma unroll
        for (int ry = 0; ry < 4; ry++) {
            const int row = threadIdx.y + ry * 8;
            ull a = mul2(wp[0], hbuf[row * 32 + threadIdx.x]);
#pragma unroll
            for (int i = 1; i < 5; i++)
                a = fma2(wp[i], hbuf[(row + i) * 32 + threadIdx.x], a);
            a = mul2(a, invp);
            float lo, hi;
            unpack2(a, lo, hi);
            obuf[cp2 * 1024 + row * 32 + threadIdx.x] = __floats2half2_rn(lo, hi);
        }
    }
    __syncthreads();

    // coalesced write-out: 32x32 px x 32B
    __half* gb = g_blur + (size_t)z * (HH * WW * 16);
    for (int i = tid; i < 2048; i += 256) {
        const int h = i & 1;
        const int px = i >> 1;
        uint32_t v[4];
#pragma unroll
        for (int j = 0; j < 4; j++)
            v[j] = *(const uint32_t*)&obuf[(4 * h + j) * 1024 + px];
        const int y = px >> 5, xg = px & 31;
        const size_t gaddr = ((size_t)(gy0 + 2 + y) * WW + (gx0 + 2 + xg)) * 16 + h * 8;
        *(uint4*)(gb + gaddr) = make_uint4(v[0], v[1], v[2], v[3]);
    }
}

// --------- Kernel 2: deformable conv, f16 mma.sync k16, ch16-interleaved tile ------
__global__ __launch_bounds__(256, 2) void deform_kernel(const float* __restrict__ sigp,
                                                        float* __restrict__ out) {
    extern __shared__ __align__(16) char smem[];
    __half* tile = (__half*)smem;                    // [32 y][48 x][16 ch]
    ull* swf = (ull*)(smem + SWF_OFF);               // [2][9][32 och][4 tig]
    int* geom = (int*)(smem + GEOM_OFF);             // 9 x {iy,ix,ipure,pad,4x half2w}
    const uint32_t tile_u = s2u(smem);

    const int tid = threadIdx.x;
    const int warp = tid >> 5;
    const int lane = tid & 31;
    const int g = lane >> 2;
    const int tig = lane & 3;

    const int b = blockIdx.z;
    const int by0 = blockIdx.y * TR;
    const int bx0 = blockIdx.x * TC;

    // stage weights
    {
        const uint4* src = (const uint4*)g_wprep;
        uint4* dst = (uint4*)swf;
        for (int i = tid; i < SWF_BYTES / 16; i += 256) dst[i] = src[i];
    }
    // tap geometry once
    if (tid < 9) {
        const float sigrate = (*sigp) * 6.0f;
        const int kyi = tid / 3 - 1;
        const int kxi = tid % 3 - 1;
        const float n2 = (float)(kyi * kyi + kxi * kxi);
        const float invn = (n2 > 0.f) ? (1.0f / sqrtf(n2)) : 0.0f;
        const float Dy = (float)kyi + sigrate * ((float)kyi * invn);
        const float Dx = (float)kxi + sigrate * ((float)kxi * invn);
        const float fy = floorf(Dy), fx = floorf(Dx);
        int iy = (int)fy, ix = (int)fx;
        const float ty = Dy - fy, tx = Dx - fx;
        iy = max(-8, min(iy, 7));
        ix = max(-8, min(ix, 7));
        int* gm = geom + tid * 8;
        gm[0] = iy;
        gm[1] = ix;
        gm[2] = (tx == 0.f && ty == 0.f) ? 1 : 0;
        __half2* gw = (__half2*)(gm + 4);
        gw[0] = __half2half2(__float2half((1.f - ty) * (1.f - tx)));
        gw[1] = __half2half2(__float2half((1.f - ty) * tx));
        gw[2] = __half2half2(__float2half(ty * (1.f - tx)));
        gw[3] = __half2half2(__float2half(ty * tx));
    }

    float acc[2][2][4][4];
#pragma unroll
    for (int rr = 0; rr < 2; rr++)
#pragma unroll
        for (int cc = 0; cc < 2; cc++)
#pragma unroll
            for (int nt = 0; nt < 4; nt++)
#pragma unroll
                for (int j = 0; j < 4; j++) acc[rr][cc][nt][j] = 0.f;

    for (int chunk = 0; chunk < 2; chunk++) {
        __syncthreads();   // tile reuse + first-iter weight/geom visibility

        // stage 16-ch tile chunk via cp.async (zero-fill outside image)
        const __half* gp = g_blur + ((size_t)b * 2 + chunk) * (HH * WW * 16);
        for (int i = tid; i < 3072; i += 256) {
            const int h = i & 1;
            const int px = i >> 1;
            const int xx = px % COLS;
            const int y = px / COLS;
            const int gy = by0 - 8 + y;
            const int gx = bx0 - 8 + xx;
            const int inb = (gy >= 0 && gy < HH && gx >= 0 && gx < WW) ? 16 : 0;
            cpasync16(tile_u + i * 16,
                      gp + ((size_t)gy * WW + gx) * 16 + h * 8, inb);
        }
        asm volatile("cp.async.commit_group;");
        asm volatile("cp.async.wait_group 0;" ::: "memory");
        __syncthreads();

        for (int tap = 0; tap < 9; tap++) {
            const int* gm = geom + tap * 8;
            const int iy = gm[0], ix = gm[1], ipure = gm[2];
            const __half2* gw = (const __half2*)(gm + 4);
            const __half2 a00 = gw[0], a01 = gw[1], a10 = gw[2], a11 = gw[3];

            // B fragments: one LDS.64 per nt (k-lane <-> channel map matches A)
            ull bv[4];
            const ull* wb = swf + (chunk * 9 + tap) * 128 + tig;
#pragma unroll
            for (int nt = 0; nt < 4; nt++) bv[nt] = wb[(nt * 8 + g) * 4];

#pragma unroll
            for (int rr = 0; rr < 2; rr++) {
#pragma unroll
                for (int cc = 0; cc < 2; cc++) {
                    const int row = 2 * warp + rr + iy + 8;
                    const int col = cc * 16 + g + ix + 8;
                    const __half* p0 = tile + ((size_t)row * COLS + col) * 16 + tig * 4;
                    ull vm, vm8;
                    if (ipure) {
                        vm = *(const ull*)p0;
                        vm8 = *(const ull*)(p0 + 128);       // col + 8
                    } else {
#pragma unroll
                        for (int m = 0; m < 2; m++) {
                            const __half* p = p0 + m * 128;
                            const __half2 c00 = *(const __half2*)p;
                            const __half2 c00b = *(const __half2*)(p + 2);
                            const __half2 c01 = *(const __half2*)(p + 16);
                            const __half2 c01b = *(const __half2*)(p + 18);
                            const __half2 c10 = *(const __half2*)(p + COLS * 16);
                            const __half2 c10b = *(const __half2*)(p + COLS * 16 + 2);
                            const __half2 c11 = *(const __half2*)(p + COLS * 16 + 16);
                            const __half2 c11b = *(const __half2*)(p + COLS * 16 + 18);
                            __half2 vlo = __hmul2(a00, c00);
                            vlo = __hfma2(a01, c01, vlo);
                            vlo = __hfma2(a10, c10, vlo);
                            vlo = __hfma2(a11, c11, vlo);
                            __half2 vhi = __hmul2(a00, c00b);
                            vhi = __hfma2(a01, c01b, vhi);
                            vhi = __hfma2(a10, c10b, vhi);
                            vhi = __hfma2(a11, c11b, vhi);
                            ull r = ((ull)*(uint32_t*)&vhi << 32) | *(uint32_t*)&vlo;
                            if (m == 0) vm = r; else vm8 = r;
                        }
                    }
                    const uint32_t A0 = (uint32_t)vm;
                    const uint32_t A2 = (uint32_t)(vm >> 32);
                    const uint32_t A1 = (uint32_t)vm8;
                    const uint32_t A3 = (uint32_t)(vm8 >> 32);
#pragma unroll
                    for (int nt = 0; nt < 4; nt++)
                        mma_f16(acc[rr][cc][nt], A0, A1, A2, A3,
                                (uint32_t)bv[nt], (uint32_t)(bv[nt] >> 32));
                }
            }
        }
    }

    // epilogue (mapping identical to R8 passing kernel)
#pragma unroll
    for (int rr = 0; rr < 2; rr++) {
        const int gy = by0 + 2 * warp + rr;
        float* ob = out + (size_t)b * OO * (HH * WW) + (size_t)gy * WW + bx0;
#pragma unroll
        for (int cc = 0; cc < 2; cc++) {
            float* oc = ob + cc * 16 + g;
#pragma unroll
            for (int nt = 0; nt < 4; nt++) {
                const int och = nt * 8 + 2 * tig;
                float* p0 = oc + (size_t)och * (HH * WW);
                float* p1 = p0 + (size_t)(HH * WW);
                p0[0] = acc[rr][cc][nt][0];
                p1[0] = acc[rr][cc][nt][1];
                p0[8] = acc[rr][cc][nt][2];
                p1[8] = acc[rr][cc][nt][3];
            }
        }
    }
}

extern "C" void kernel_launch(void* const* d_in, const int* in_sizes, int n_in,
                              void* d_out, int out_size) {
    const float* x = nullptr;
    const float* sig = nullptr;
    const float* wgt = nullptr;
    for (int i = 0; i < n_in; i++) {
        if (in_sizes[i] == 1) sig = (const float*)d_in[i];
        else if (in_sizes[i] == OO * CC * 9) wgt = (const float*)d_in[i];
        else x = (const float*)d_in[i];
    }
    float* out = (float*)d_out;

    wprep_kernel<<<36, 256>>>(wgt);

    cudaFuncSetAttribute(blur_kernel,
                         cudaFuncAttributeMaxDynamicSharedMemorySize, B_SMEM_DYN);
    dim3 bgrid(WW / 32, HH / 32, BB * 2);
    blur_kernel<<<bgrid, dim3(32, 8), B_SMEM_DYN>>>(x, sig);

    cudaFuncSetAttribute(deform_kernel,
                         cudaFuncAttributeMaxDynamicSharedMemorySize, SMEM_DYN);
    dim3 dgrid(WW / TC, HH / TR, BB);
    deform_kernel<<<dgrid, 256, SMEM_DYN>>>(sig, out);
}